// round 12
// baseline (speedup 1.0000x reference)
#include <cuda_runtime.h>
#include <cuda_fp16.h>
#include <stdint.h>

// ---------------------------------------------------------------------------
// QLoRA linear on sm_103 (portable-PTX tensor path: mma.sync HMMA).
//   out[M, 4096] = x[M, 4096] @ (dequant_nf4(codes, scales) + 2.0 * B@A)^T
//
//   Prologue 1: W_eff fp16 [4096, 4096]  (dequant + folded rank-16 LoRA)
//   Prologue 2: x fp16 [M, 4096]
//   Main: fp16 HMMA GEMM, fp32 accum, C = Xh @ Wh^T (both K-major -> NT)
//         BM=128, BN=256, BK=32, 256 threads (warp grid 2x4, warptile 64x64),
//         4-stage cp.async pipeline, ONE __syncthreads per iteration,
//         120KB dynamic smem.
//   Rationale: warptile 64x64 cuts smem fragment re-reads to ~94KB/iter
//   (< crossbar budget per MMA interval); 4 stages restore latency hiding
//   with only 8 warps.
//   Operands via __device__ globals from device code (host-side symbol args
//   silently read the host shadow through ATS on GB300 -> zeros).
// ---------------------------------------------------------------------------

#define D_INF   4096
#define D_OUTF  4096
#define RANK    16
#define LORA_SCALING 2.0f
#define MAX_M   8192

#define BM 128
#define BN 256
#define BK 32
#define NIT (D_INF / BK)            // 128
#define STAGES 4

// smem tile row: 32 halfs = 64B data + 16B pad = 80B stride.
// ldmatrix 8-row phase banks: r*20 mod 32 -> {0,20,8,28,16,4,24,12} conflict-free.
#define ROW_B 80
#define A_BYTES (BM * ROW_B)                 // 10240
#define B_BYTES (BN * ROW_B)                 // 20480
#define STAGE_BYTES (A_BYTES + B_BYTES)      // 30720
#define SMEM_TOTAL (STAGES * STAGE_BYTES)    // 122880

__constant__ float c_nf4[16] = {
    -1.0f, -0.6961928009986877f, -0.5250730514526367f, -0.39491748809814453f,
    -0.28444138169288635f, -0.18477343022823334f, -0.09105003625154495f, 0.0f,
    0.07958029955625534f, 0.16093020141124725f, 0.24611230194568634f,
    0.33791524171829224f, 0.44070982933044434f, 0.5626170039176941f,
    0.7229568362236023f, 1.0f
};

__device__ __align__(128) __half g_Xh[(size_t)MAX_M * D_INF];    // 64 MiB
__device__ __align__(128) __half g_Wh[(size_t)D_OUTF * D_INF];   // 32 MiB

// ------------------------------ PTX helpers -------------------------------
__device__ __forceinline__ uint32_t smem_u32(const void* p) {
    uint32_t a;
    asm("{ .reg .u64 t; cvta.to.shared.u64 t, %1; cvt.u32.u64 %0, t; }"
        : "=r"(a) : "l"(p));
    return a;
}

__device__ __forceinline__ void cp_async16(uint32_t dst, const void* src) {
    asm volatile("cp.async.cg.shared.global [%0], [%1], 16;"
                 :: "r"(dst), "l"(src) : "memory");
}
#define CP_COMMIT() asm volatile("cp.async.commit_group;" ::: "memory")
#define CP_WAIT(n)  asm volatile("cp.async.wait_group %0;" :: "n"(n) : "memory")

#define LDSM_X4(r, addr) \
    asm volatile("ldmatrix.sync.aligned.m8n8.x4.shared.b16 {%0,%1,%2,%3}, [%4];" \
                 : "=r"((r)[0]), "=r"((r)[1]), "=r"((r)[2]), "=r"((r)[3]) \
                 : "r"(addr))

__device__ __forceinline__ void mma16816(float* c, const uint32_t* a,
                                         uint32_t b0, uint32_t b1) {
    asm volatile(
        "mma.sync.aligned.m16n8k16.row.col.f32.f16.f16.f32 "
        "{%0,%1,%2,%3}, {%4,%5,%6,%7}, {%8,%9}, {%0,%1,%2,%3};"
        : "+f"(c[0]), "+f"(c[1]), "+f"(c[2]), "+f"(c[3])
        : "r"(a[0]), "r"(a[1]), "r"(a[2]), "r"(a[3]), "r"(b0), "r"(b1));
}

// ---------------------------------------------------------------------------
// Prologue 1: W_eff fp16 = nf4[code]*scale + 2.0 * (lora_B @ lora_A)
// 4 consecutive elements per thread.
// ---------------------------------------------------------------------------
__global__ void build_wh_kernel(const int*   __restrict__ codes,
                                const float* __restrict__ scales,
                                const float* __restrict__ lora_A,
                                const float* __restrict__ lora_B)
{
    const int gid = blockIdx.x * blockDim.x + threadIdx.x;   // < 4,194,304
    const int p4 = gid & 1023;         // group of 4 elems within row
    const int o  = gid >> 10;          // output feature

    const int4 cc = ((const int4*)codes)[gid];
    const float s = scales[o * (D_INF / 64) + (p4 >> 4)];

    float l0 = 0.0f, l1 = 0.0f, l2 = 0.0f, l3 = 0.0f;
#pragma unroll
    for (int r = 0; r < RANK; r++) {
        const float4 a4 = ((const float4*)(lora_A + r * D_INF))[p4];
        const float  b  = lora_B[o * RANK + r];
        l0 = fmaf(a4.x, b, l0);
        l1 = fmaf(a4.y, b, l1);
        l2 = fmaf(a4.z, b, l2);
        l3 = fmaf(a4.w, b, l3);
    }

    const float w0 = fmaf(c_nf4[cc.x & 15], s, LORA_SCALING * l0);
    const float w1 = fmaf(c_nf4[cc.y & 15], s, LORA_SCALING * l1);
    const float w2 = fmaf(c_nf4[cc.z & 15], s, LORA_SCALING * l2);
    const float w3 = fmaf(c_nf4[cc.w & 15], s, LORA_SCALING * l3);

    const __half2 h01 = __floats2half2_rn(w0, w1);
    const __half2 h23 = __floats2half2_rn(w2, w3);
    uint2 pk;
    pk.x = *(const uint32_t*)&h01;
    pk.y = *(const uint32_t*)&h23;
    ((uint2*)(g_Wh + (size_t)o * D_INF))[p4] = pk;
}

// ---------------------------------------------------------------------------
// Prologue 2: x -> fp16 (4 elements per thread)
// ---------------------------------------------------------------------------
__global__ void build_xh_kernel(const float* __restrict__ x)
{
    const int gid = blockIdx.x * blockDim.x + threadIdx.x;   // < M*1024
    const float4 v = ((const float4*)x)[gid];
    const __half2 h01 = __floats2half2_rn(v.x, v.y);
    const __half2 h23 = __floats2half2_rn(v.z, v.w);
    uint2 pk;
    pk.x = *(const uint32_t*)&h01;
    pk.y = *(const uint32_t*)&h23;
    ((uint2*)g_Xh)[gid] = pk;
}

// ---------------------------------------------------------------------------
// Main GEMM: C[M, 4096] = g_Xh @ g_Wh^T, fp32 accum.
// 256 threads = 8 warps, warp grid 2(M) x 4(N), warptile 64x64.
// 4-stage pipeline, one barrier per iteration.
// ---------------------------------------------------------------------------
__global__ __launch_bounds__(256, 1)
void hgemm_nt_kernel(float* __restrict__ C)
{
    extern __shared__ __align__(128) uint8_t smem_raw[];
    const uint32_t sb = smem_u32(smem_raw);

    const int tid  = threadIdx.x;
    const int lane = tid & 31;
    const int wid  = tid >> 5;
    const int wm   = wid >> 2;        // 0..1  (M 64-half of CTA tile)
    const int wn   = wid & 3;         // 0..3  (N 64-quarter)
    const int bn   = blockIdx.x;
    const int bm   = blockIdx.y;

    // --- global->smem geometry: 4 threads/row (16B each), 64 rows/pass ---
    const int lrow = tid >> 2;                 // 0..63
    const int lchk = (tid & 3) << 4;           // 0,16,32,48 bytes
    const __half* Ag = g_Xh + (size_t)(bm * BM + lrow) * D_INF + (tid & 3) * 8;
    const __half* Bg = g_Wh + (size_t)(bn * BN + lrow) * D_INF + (tid & 3) * 8;

    const uint32_t dA = sb + lrow * ROW_B + lchk;               // + stage*STAGE
    const uint32_t dB = sb + A_BYTES + lrow * ROW_B + lchk;

    // --- ldmatrix per-lane byte offsets within a tile ---
    const int lr = lane & 7;
    const uint32_t aoff = (uint32_t)((lr + ((lane >> 3) & 1) * 8) * ROW_B + (lane >> 4) * 16);
    const uint32_t boff = (uint32_t)((lr + (lane >> 4) * 8) * ROW_B + ((lane >> 3) & 1) * 16);

    float acc[4][8][4];
#pragma unroll
    for (int m = 0; m < 4; m++)
#pragma unroll
        for (int n = 0; n < 8; n++)
#pragma unroll
            for (int t = 0; t < 4; t++) acc[m][n][t] = 0.0f;

    // --- prefetch stages 0..STAGES-2 ---
#pragma unroll
    for (int s = 0; s < STAGES - 1; s++) {
        const uint32_t so = (uint32_t)s * STAGE_BYTES;
        const size_t k0 = (size_t)s * BK;
        cp_async16(dA + so,              Ag + k0);
        cp_async16(dA + so + 64 * ROW_B, Ag + (size_t)64 * D_INF + k0);
#pragma unroll
        for (int j = 0; j < 4; j++)
            cp_async16(dB + so + j * 64 * ROW_B, Bg + (size_t)(j * 64) * D_INF + k0);
        CP_COMMIT();
    }

    int slot_c = 0;                   // slot holding stage i
    int slot_l = STAGES - 1;          // slot receiving stage i+STAGES-1
    for (int i = 0; i < NIT; i++) {
        CP_WAIT(STAGES - 2);          // stage i resident (this thread)
        __syncthreads();              // resident block-wide; orders last iter's
                                      // compute of slot_l before its refill.

        const int L = i + STAGES - 1;
        if (L < NIT) {
            const uint32_t so = (uint32_t)slot_l * STAGE_BYTES;
            const size_t k0 = (size_t)L * BK;
            cp_async16(dA + so,              Ag + k0);
            cp_async16(dA + so + 64 * ROW_B, Ag + (size_t)64 * D_INF + k0);
#pragma unroll
            for (int j = 0; j < 4; j++)
                cp_async16(dB + so + j * 64 * ROW_B, Bg + (size_t)(j * 64) * D_INF + k0);
            CP_COMMIT();
        }

        // compute stage i from slot_c
        const uint32_t so = (uint32_t)slot_c * STAGE_BYTES;
        const uint32_t ab = sb + so + (uint32_t)(wm * 64) * ROW_B + aoff;
        const uint32_t bb = sb + so + A_BYTES + (uint32_t)(wn * 64) * ROW_B + boff;

#pragma unroll
        for (int kf = 0; kf < 2; kf++) {
            uint32_t af[4][4], bf[4][4];
#pragma unroll
            for (int mf = 0; mf < 4; mf++)
                LDSM_X4(af[mf], ab + (uint32_t)(mf * 16) * ROW_B + kf * 32);
#pragma unroll
            for (int nf2 = 0; nf2 < 4; nf2++)
                LDSM_X4(bf[nf2], bb + (uint32_t)(nf2 * 16) * ROW_B + kf * 32);
#pragma unroll
            for (int mf = 0; mf < 4; mf++)
#pragma unroll
                for (int nf = 0; nf < 8; nf++)
                    mma16816(acc[mf][nf], af[mf],
                             bf[nf >> 1][(nf & 1) * 2], bf[nf >> 1][(nf & 1) * 2 + 1]);
        }

        slot_c = (slot_c == STAGES - 1) ? 0 : slot_c + 1;
        slot_l = (slot_l == STAGES - 1) ? 0 : slot_l + 1;
    }

    // --- epilogue: c0,c1 -> (row, col); c2,c3 -> (row+8, col) ---
#pragma unroll
    for (int mf = 0; mf < 4; mf++) {
        const int row = bm * BM + wm * 64 + mf * 16 + (lane >> 2);
        float* r0 = C + (size_t)row * D_OUTF + bn * BN + wn * 64 + (lane & 3) * 2;
        float* r1 = r0 + (size_t)8 * D_OUTF;
#pragma unroll
        for (int nf = 0; nf < 8; nf++) {
            *(float2*)(r0 + nf * 8) = make_float2(acc[mf][nf][0], acc[mf][nf][1]);
            *(float2*)(r1 + nf * 8) = make_float2(acc[mf][nf][2], acc[mf][nf][3]);
        }
    }
}

// ---------------------------------------------------------------------------
// kernel_launch — graph-capturable, allocation-free.
// Inputs: x[f32], codes[i32], scales[f32], lora_A[f32], lora_B[f32]; out f32.
// ---------------------------------------------------------------------------
extern "C" void kernel_launch(void* const* d_in, const int* in_sizes, int n_in,
                              void* d_out, int out_size)
{
    const float* x      = (const float*)d_in[0];
    const int*   codes  = (const int*)  d_in[1];
    const float* scales = (const float*)d_in[2];
    const float* lora_A = (const float*)d_in[3];
    const float* lora_B = (const float*)d_in[4];
    float*       out    = (float*)d_out;

    const int M = in_sizes[0] / D_INF;   // 8192

    cudaFuncSetAttribute(hgemm_nt_kernel,
                         cudaFuncAttributeMaxDynamicSharedMemorySize, SMEM_TOTAL);

    build_wh_kernel<<<(D_OUTF * 1024) / 256, 256>>>(codes, scales, lora_A, lora_B);
    build_xh_kernel<<<(M * 1024) / 256, 256>>>(x);

    dim3 grid(D_OUTF / BN, M / BM);   // (16, 64)
    hgemm_nt_kernel<<<grid, 256, SMEM_TOTAL>>>(out);

    (void)n_in; (void)out_size;
}

// round 13
// speedup vs baseline: 1.0900x; 1.0900x over previous
#include <cuda_runtime.h>
#include <cuda_fp16.h>
#include <stdint.h>

// ---------------------------------------------------------------------------
// QLoRA linear on sm_103 (portable-PTX tensor path: mma.sync HMMA).
//   out[M, 4096] = x[M, 4096] @ (dequant_nf4(codes, scales) + 2.0 * B@A)^T
//
//   Prologue 1: W_eff fp16 [4096, 4096]  (dequant + folded rank-16 LoRA)
//   Prologue 2: x fp16 [M, 4096]
//   Main: fp16 HMMA GEMM, fp32 accum, C = Xh @ Wh^T (both K-major -> NT)
//         BM=BN=128, BK=32, 256 threads (warp grid 2x4, warptile 64x32),
//         3-stage cp.async pipeline, ONE __syncthreads per iteration,
//         60KB dynamic smem -> 2 CTAs/SM (16 warps/SM, independent barriers).
//   Empirical law from R9-R12: 16 warps/SM required to hide mma.sync latency;
//   2 independent CTAs/SM beat one barrier-coupled fat CTA.
//   Operands via __device__ globals from device code (host-side symbol args
//   silently read the host shadow through ATS on GB300 -> zeros).
// ---------------------------------------------------------------------------

#define D_INF   4096
#define D_OUTF  4096
#define RANK    16
#define LORA_SCALING 2.0f
#define MAX_M   8192

#define BM 128
#define BN 128
#define BK 32
#define NIT (D_INF / BK)            // 128
#define STAGES 3

// smem tile row: 32 halfs = 64B data + 16B pad = 80B stride.
// ldmatrix 8-row phase banks: r*20 mod 32 -> {0,20,8,28,16,4,24,12} conflict-free.
#define ROW_B 80
#define A_BYTES (BM * ROW_B)                 // 10240
#define B_BYTES (BN * ROW_B)                 // 10240
#define STAGE_BYTES (A_BYTES + B_BYTES)      // 20480
#define SMEM_TOTAL (STAGES * STAGE_BYTES)    // 61440 (x2 CTAs = 120KB/SM)

__constant__ float c_nf4[16] = {
    -1.0f, -0.6961928009986877f, -0.5250730514526367f, -0.39491748809814453f,
    -0.28444138169288635f, -0.18477343022823334f, -0.09105003625154495f, 0.0f,
    0.07958029955625534f, 0.16093020141124725f, 0.24611230194568634f,
    0.33791524171829224f, 0.44070982933044434f, 0.5626170039176941f,
    0.7229568362236023f, 1.0f
};

__device__ __align__(128) __half g_Xh[(size_t)MAX_M * D_INF];    // 64 MiB
__device__ __align__(128) __half g_Wh[(size_t)D_OUTF * D_INF];   // 32 MiB

// ------------------------------ PTX helpers -------------------------------
__device__ __forceinline__ uint32_t smem_u32(const void* p) {
    uint32_t a;
    asm("{ .reg .u64 t; cvta.to.shared.u64 t, %1; cvt.u32.u64 %0, t; }"
        : "=r"(a) : "l"(p));
    return a;
}

__device__ __forceinline__ void cp_async16(uint32_t dst, const void* src) {
    asm volatile("cp.async.cg.shared.global [%0], [%1], 16;"
                 :: "r"(dst), "l"(src) : "memory");
}
#define CP_COMMIT() asm volatile("cp.async.commit_group;" ::: "memory")
#define CP_WAIT(n)  asm volatile("cp.async.wait_group %0;" :: "n"(n) : "memory")

#define LDSM_X4(r, addr) \
    asm volatile("ldmatrix.sync.aligned.m8n8.x4.shared.b16 {%0,%1,%2,%3}, [%4];" \
                 : "=r"((r)[0]), "=r"((r)[1]), "=r"((r)[2]), "=r"((r)[3]) \
                 : "r"(addr))

__device__ __forceinline__ void mma16816(float* c, const uint32_t* a,
                                         uint32_t b0, uint32_t b1) {
    asm volatile(
        "mma.sync.aligned.m16n8k16.row.col.f32.f16.f16.f32 "
        "{%0,%1,%2,%3}, {%4,%5,%6,%7}, {%8,%9}, {%0,%1,%2,%3};"
        : "+f"(c[0]), "+f"(c[1]), "+f"(c[2]), "+f"(c[3])
        : "r"(a[0]), "r"(a[1]), "r"(a[2]), "r"(a[3]), "r"(b0), "r"(b1));
}

// ---------------------------------------------------------------------------
// Prologue 1: W_eff fp16 = nf4[code]*scale + 2.0 * (lora_B @ lora_A)
// 4 consecutive elements per thread.
// ---------------------------------------------------------------------------
__global__ void build_wh_kernel(const int*   __restrict__ codes,
                                const float* __restrict__ scales,
                                const float* __restrict__ lora_A,
                                const float* __restrict__ lora_B)
{
    const int gid = blockIdx.x * blockDim.x + threadIdx.x;   // < 4,194,304
    const int p4 = gid & 1023;         // group of 4 elems within row
    const int o  = gid >> 10;          // output feature

    const int4 cc = ((const int4*)codes)[gid];
    const float s = scales[o * (D_INF / 64) + (p4 >> 4)];

    float l0 = 0.0f, l1 = 0.0f, l2 = 0.0f, l3 = 0.0f;
#pragma unroll
    for (int r = 0; r < RANK; r++) {
        const float4 a4 = ((const float4*)(lora_A + r * D_INF))[p4];
        const float  b  = lora_B[o * RANK + r];
        l0 = fmaf(a4.x, b, l0);
        l1 = fmaf(a4.y, b, l1);
        l2 = fmaf(a4.z, b, l2);
        l3 = fmaf(a4.w, b, l3);
    }

    const float w0 = fmaf(c_nf4[cc.x & 15], s, LORA_SCALING * l0);
    const float w1 = fmaf(c_nf4[cc.y & 15], s, LORA_SCALING * l1);
    const float w2 = fmaf(c_nf4[cc.z & 15], s, LORA_SCALING * l2);
    const float w3 = fmaf(c_nf4[cc.w & 15], s, LORA_SCALING * l3);

    const __half2 h01 = __floats2half2_rn(w0, w1);
    const __half2 h23 = __floats2half2_rn(w2, w3);
    uint2 pk;
    pk.x = *(const uint32_t*)&h01;
    pk.y = *(const uint32_t*)&h23;
    ((uint2*)(g_Wh + (size_t)o * D_INF))[p4] = pk;
}

// ---------------------------------------------------------------------------
// Prologue 2: x -> fp16 (4 elements per thread)
// ---------------------------------------------------------------------------
__global__ void build_xh_kernel(const float* __restrict__ x)
{
    const int gid = blockIdx.x * blockDim.x + threadIdx.x;   // < M*1024
    const float4 v = ((const float4*)x)[gid];
    const __half2 h01 = __floats2half2_rn(v.x, v.y);
    const __half2 h23 = __floats2half2_rn(v.z, v.w);
    uint2 pk;
    pk.x = *(const uint32_t*)&h01;
    pk.y = *(const uint32_t*)&h23;
    ((uint2*)g_Xh)[gid] = pk;
}

// ---------------------------------------------------------------------------
// Main GEMM: C[M, 4096] = g_Xh @ g_Wh^T, fp32 accum.
// 256 threads = 8 warps, warp grid 2(M) x 4(N), warptile 64x32.
// 3-stage pipeline, one barrier per iteration, 2 CTAs/SM.
// ---------------------------------------------------------------------------
__global__ __launch_bounds__(256, 2)
void hgemm_nt_kernel(float* __restrict__ C)
{
    extern __shared__ __align__(128) uint8_t smem_raw[];
    const uint32_t sb = smem_u32(smem_raw);

    const int tid  = threadIdx.x;
    const int lane = tid & 31;
    const int wid  = tid >> 5;
    const int wm   = wid >> 2;        // 0..1  (M 64-half of CTA tile)
    const int wn   = wid & 3;         // 0..3  (N 32-slice)
    const int bn   = blockIdx.x;
    const int bm   = blockIdx.y;

    // --- global->smem geometry: 4 threads/row (16B each), 64 rows/pass ---
    const int lrow = tid >> 2;                 // 0..63
    const int lchk = (tid & 3) << 4;           // 0,16,32,48 bytes
    const __half* Ag = g_Xh + (size_t)(bm * BM + lrow) * D_INF + (tid & 3) * 8;
    const __half* Bg = g_Wh + (size_t)(bn * BN + lrow) * D_INF + (tid & 3) * 8;

    const uint32_t dA = sb + lrow * ROW_B + lchk;               // + stage*STAGE
    const uint32_t dB = sb + A_BYTES + lrow * ROW_B + lchk;

    // --- ldmatrix per-lane byte offsets within a tile ---
    const int lr = lane & 7;
    const uint32_t aoff = (uint32_t)((lr + ((lane >> 3) & 1) * 8) * ROW_B + (lane >> 4) * 16);
    const uint32_t boff = (uint32_t)((lr + (lane >> 4) * 8) * ROW_B + ((lane >> 3) & 1) * 16);

    float acc[4][4][4];
#pragma unroll
    for (int m = 0; m < 4; m++)
#pragma unroll
        for (int n = 0; n < 4; n++)
#pragma unroll
            for (int t = 0; t < 4; t++) acc[m][n][t] = 0.0f;

    // --- prefetch stages 0..STAGES-2 ---
#pragma unroll
    for (int s = 0; s < STAGES - 1; s++) {
        const uint32_t so = (uint32_t)s * STAGE_BYTES;
        const size_t k0 = (size_t)s * BK;
        cp_async16(dA + so,              Ag + k0);
        cp_async16(dA + so + 64 * ROW_B, Ag + (size_t)64 * D_INF + k0);
        cp_async16(dB + so,              Bg + k0);
        cp_async16(dB + so + 64 * ROW_B, Bg + (size_t)64 * D_INF + k0);
        CP_COMMIT();
    }

    int slot_c = 0;                   // slot holding stage i
    int slot_l = STAGES - 1;          // slot receiving stage i+STAGES-1
    for (int i = 0; i < NIT; i++) {
        CP_WAIT(STAGES - 2);          // stage i resident (this thread)
        __syncthreads();              // resident block-wide; orders last iter's
                                      // compute of slot_l before its refill.

        const int L = i + STAGES - 1;
        if (L < NIT) {
            const uint32_t so = (uint32_t)slot_l * STAGE_BYTES;
            const size_t k0 = (size_t)L * BK;
            cp_async16(dA + so,              Ag + k0);
            cp_async16(dA + so + 64 * ROW_B, Ag + (size_t)64 * D_INF + k0);
            cp_async16(dB + so,              Bg + k0);
            cp_async16(dB + so + 64 * ROW_B, Bg + (size_t)64 * D_INF + k0);
            CP_COMMIT();
        }

        // compute stage i from slot_c
        const uint32_t so = (uint32_t)slot_c * STAGE_BYTES;
        const uint32_t ab = sb + so + (uint32_t)(wm * 64) * ROW_B + aoff;
        const uint32_t bb = sb + so + A_BYTES + (uint32_t)(wn * 32) * ROW_B + boff;

#pragma unroll
        for (int kf = 0; kf < 2; kf++) {
            uint32_t af[4][4], bf[2][4];
#pragma unroll
            for (int mf = 0; mf < 4; mf++)
                LDSM_X4(af[mf], ab + (uint32_t)(mf * 16) * ROW_B + kf * 32);
#pragma unroll
            for (int nf2 = 0; nf2 < 2; nf2++)
                LDSM_X4(bf[nf2], bb + (uint32_t)(nf2 * 16) * ROW_B + kf * 32);
#pragma unroll
            for (int mf = 0; mf < 4; mf++)
#pragma unroll
                for (int nf = 0; nf < 4; nf++)
                    mma16816(acc[mf][nf], af[mf],
                             bf[nf >> 1][(nf & 1) * 2], bf[nf >> 1][(nf & 1) * 2 + 1]);
        }

        slot_c = (slot_c == STAGES - 1) ? 0 : slot_c + 1;
        slot_l = (slot_l == STAGES - 1) ? 0 : slot_l + 1;
    }

    // --- epilogue: c0,c1 -> (row, col); c2,c3 -> (row+8, col) ---
#pragma unroll
    for (int mf = 0; mf < 4; mf++) {
        const int row = bm * BM + wm * 64 + mf * 16 + (lane >> 2);
        float* r0 = C + (size_t)row * D_OUTF + bn * BN + wn * 32 + (lane & 3) * 2;
        float* r1 = r0 + (size_t)8 * D_OUTF;
#pragma unroll
        for (int nf = 0; nf < 4; nf++) {
            *(float2*)(r0 + nf * 8) = make_float2(acc[mf][nf][0], acc[mf][nf][1]);
            *(float2*)(r1 + nf * 8) = make_float2(acc[mf][nf][2], acc[mf][nf][3]);
        }
    }
}

// ---------------------------------------------------------------------------
// kernel_launch — graph-capturable, allocation-free.
// Inputs: x[f32], codes[i32], scales[f32], lora_A[f32], lora_B[f32]; out f32.
// ---------------------------------------------------------------------------
extern "C" void kernel_launch(void* const* d_in, const int* in_sizes, int n_in,
                              void* d_out, int out_size)
{
    const float* x      = (const float*)d_in[0];
    const int*   codes  = (const int*)  d_in[1];
    const float* scales = (const float*)d_in[2];
    const float* lora_A = (const float*)d_in[3];
    const float* lora_B = (const float*)d_in[4];
    float*       out    = (float*)d_out;

    const int M = in_sizes[0] / D_INF;   // 8192

    cudaFuncSetAttribute(hgemm_nt_kernel,
                         cudaFuncAttributeMaxDynamicSharedMemorySize, SMEM_TOTAL);

    build_wh_kernel<<<(D_OUTF * 1024) / 256, 256>>>(codes, scales, lora_A, lora_B);
    build_xh_kernel<<<(M * 1024) / 256, 256>>>(x);

    dim3 grid(D_OUTF / BN, M / BM);   // (32, 64)
    hgemm_nt_kernel<<<grid, 256, SMEM_TOTAL>>>(out);

    (void)n_in; (void)out_size;
}

// round 14
// speedup vs baseline: 1.2718x; 1.1668x over previous
#include <cuda_runtime.h>
#include <cuda_fp16.h>
#include <stdint.h>

// ---------------------------------------------------------------------------
// QLoRA linear on sm_103 (portable-PTX tensor path: mma.sync HMMA).
//   out[M, 4096] = x[M, 4096] @ (dequant_nf4(codes, scales) + 2.0 * B@A)^T
//
//   Prologue (single launch, grid split):
//     W_eff fp16 [4096,4096] = nf4[code]*scale + 2*(B@A);  x -> fp16.
//   Main: fp16 HMMA GEMM, fp32 accum, C = Xh @ Wh^T (both K-major -> NT)
//         BM=BN=128, BK=64, 256 threads (warp grid 2x4, warptile 64x32),
//         2-stage cp.async double buffer, ONE __syncthreads per iteration,
//         64 iterations, 72KB dynamic smem -> 2 CTAs/SM (16 warps/SM).
//   Empirical laws from R9-R13: (1) 16 warps/SM required to hide mma.sync
//   latency; (2) 2 independent CTAs/SM beat one fat CTA; (3) per-iteration
//   fixed costs are the remaining 39% -> halve iteration count via BK=64.
//   Operands via __device__ globals from device code (host-side symbol args
//   silently read the host shadow through ATS on GB300 -> zeros).
// ---------------------------------------------------------------------------

#define D_INF   4096
#define D_OUTF  4096
#define RANK    16
#define LORA_SCALING 2.0f
#define MAX_M   8192

#define BM 128
#define BN 128
#define BK 64
#define NIT (D_INF / BK)            // 64
#define STAGES 2

// smem tile row: 64 halfs = 128B data + 16B pad = 144B stride.
// ldmatrix 8-row phase banks: r*36 mod 32 = 4r -> 8 distinct 16B groups.
#define ROW_B 144
#define A_BYTES (BM * ROW_B)                 // 18432
#define B_BYTES (BN * ROW_B)                 // 18432
#define STAGE_BYTES (A_BYTES + B_BYTES)      // 36864
#define SMEM_TOTAL (STAGES * STAGE_BYTES)    // 73728 (x2 CTAs = 144KB/SM)

__constant__ float c_nf4[16] = {
    -1.0f, -0.6961928009986877f, -0.5250730514526367f, -0.39491748809814453f,
    -0.28444138169288635f, -0.18477343022823334f, -0.09105003625154495f, 0.0f,
    0.07958029955625534f, 0.16093020141124725f, 0.24611230194568634f,
    0.33791524171829224f, 0.44070982933044434f, 0.5626170039176941f,
    0.7229568362236023f, 1.0f
};

__device__ __align__(128) __half g_Xh[(size_t)MAX_M * D_INF];    // 64 MiB
__device__ __align__(128) __half g_Wh[(size_t)D_OUTF * D_INF];   // 32 MiB

// ------------------------------ PTX helpers -------------------------------
__device__ __forceinline__ uint32_t smem_u32(const void* p) {
    uint32_t a;
    asm("{ .reg .u64 t; cvta.to.shared.u64 t, %1; cvt.u32.u64 %0, t; }"
        : "=r"(a) : "l"(p));
    return a;
}

__device__ __forceinline__ void cp_async16(uint32_t dst, const void* src) {
    asm volatile("cp.async.cg.shared.global [%0], [%1], 16;"
                 :: "r"(dst), "l"(src) : "memory");
}
#define CP_COMMIT() asm volatile("cp.async.commit_group;" ::: "memory")
#define CP_WAIT(n)  asm volatile("cp.async.wait_group %0;" :: "n"(n) : "memory")

#define LDSM_X4(r, addr) \
    asm volatile("ldmatrix.sync.aligned.m8n8.x4.shared.b16 {%0,%1,%2,%3}, [%4];" \
                 : "=r"((r)[0]), "=r"((r)[1]), "=r"((r)[2]), "=r"((r)[3]) \
                 : "r"(addr))

__device__ __forceinline__ void mma16816(float* c, const uint32_t* a,
                                         uint32_t b0, uint32_t b1) {
    asm volatile(
        "mma.sync.aligned.m16n8k16.row.col.f32.f16.f16.f32 "
        "{%0,%1,%2,%3}, {%4,%5,%6,%7}, {%8,%9}, {%0,%1,%2,%3};"
        : "+f"(c[0]), "+f"(c[1]), "+f"(c[2]), "+f"(c[3])
        : "r"(a[0]), "r"(a[1]), "r"(a[2]), "r"(a[3]), "r"(b0), "r"(b1));
}

// ---------------------------------------------------------------------------
// Merged prologue. Blocks [0, WBLK): build W_eff; blocks [WBLK, WBLK+XBLK):
// convert x. 4 consecutive elements per thread in both halves.
// ---------------------------------------------------------------------------
#define WBLK (D_OUTF * 1024 / 256)          // 16384
__global__ void build_inputs_kernel(const float* __restrict__ x,
                                    const int*   __restrict__ codes,
                                    const float* __restrict__ scales,
                                    const float* __restrict__ lora_A,
                                    const float* __restrict__ lora_B)
{
    if (blockIdx.x < WBLK) {
        const int gid = blockIdx.x * blockDim.x + threadIdx.x;   // < 4,194,304
        const int p4 = gid & 1023;         // group of 4 elems within row
        const int o  = gid >> 10;          // output feature

        const int4 cc = ((const int4*)codes)[gid];
        const float s = scales[o * (D_INF / 64) + (p4 >> 4)];

        float l0 = 0.0f, l1 = 0.0f, l2 = 0.0f, l3 = 0.0f;
#pragma unroll
        for (int r = 0; r < RANK; r++) {
            const float4 a4 = ((const float4*)(lora_A + r * D_INF))[p4];
            const float  b  = lora_B[o * RANK + r];
            l0 = fmaf(a4.x, b, l0);
            l1 = fmaf(a4.y, b, l1);
            l2 = fmaf(a4.z, b, l2);
            l3 = fmaf(a4.w, b, l3);
        }

        const float w0 = fmaf(c_nf4[cc.x & 15], s, LORA_SCALING * l0);
        const float w1 = fmaf(c_nf4[cc.y & 15], s, LORA_SCALING * l1);
        const float w2 = fmaf(c_nf4[cc.z & 15], s, LORA_SCALING * l2);
        const float w3 = fmaf(c_nf4[cc.w & 15], s, LORA_SCALING * l3);

        const __half2 h01 = __floats2half2_rn(w0, w1);
        const __half2 h23 = __floats2half2_rn(w2, w3);
        uint2 pk;
        pk.x = *(const uint32_t*)&h01;
        pk.y = *(const uint32_t*)&h23;
        ((uint2*)(g_Wh + (size_t)o * D_INF))[p4] = pk;
    } else {
        const int gid = (blockIdx.x - WBLK) * blockDim.x + threadIdx.x;
        const float4 v = ((const float4*)x)[gid];
        const __half2 h01 = __floats2half2_rn(v.x, v.y);
        const __half2 h23 = __floats2half2_rn(v.z, v.w);
        uint2 pk;
        pk.x = *(const uint32_t*)&h01;
        pk.y = *(const uint32_t*)&h23;
        ((uint2*)g_Xh)[gid] = pk;
    }
}

// ---------------------------------------------------------------------------
// Main GEMM: C[M, 4096] = g_Xh @ g_Wh^T, fp32 accum.
// 256 threads = 8 warps, warp grid 2(M) x 4(N), warptile 64x32.
// BK=64, 2-stage double buffer, one barrier per iteration, 2 CTAs/SM.
// ---------------------------------------------------------------------------
__global__ __launch_bounds__(256, 2)
void hgemm_nt_kernel(float* __restrict__ C)
{
    extern __shared__ __align__(128) uint8_t smem_raw[];
    const uint32_t sb = smem_u32(smem_raw);

    const int tid  = threadIdx.x;
    const int lane = tid & 31;
    const int wid  = tid >> 5;
    const int wm   = wid >> 2;        // 0..1  (M 64-half of CTA tile)
    const int wn   = wid & 3;         // 0..3  (N 32-slice)
    const int bn   = blockIdx.x;
    const int bm   = blockIdx.y;

    // --- global->smem geometry: 8 threads/row (16B each), 32 rows/pass, 4 passes ---
    const int lrow = tid >> 3;                 // 0..31
    const int lchk = (tid & 7) << 4;           // 0..112 bytes
    const __half* Ag = g_Xh + (size_t)(bm * BM + lrow) * D_INF + (tid & 7) * 8;
    const __half* Bg = g_Wh + (size_t)(bn * BN + lrow) * D_INF + (tid & 7) * 8;

    const uint32_t dA = sb + lrow * ROW_B + lchk;               // + stage*STAGE
    const uint32_t dB = sb + A_BYTES + lrow * ROW_B + lchk;

    // --- ldmatrix per-lane byte offsets within a tile ---
    const int lr = lane & 7;
    const uint32_t aoff = (uint32_t)((lr + ((lane >> 3) & 1) * 8) * ROW_B + (lane >> 4) * 16);
    const uint32_t boff = (uint32_t)((lr + (lane >> 4) * 8) * ROW_B + ((lane >> 3) & 1) * 16);

    float acc[4][4][4];
#pragma unroll
    for (int m = 0; m < 4; m++)
#pragma unroll
        for (int n = 0; n < 4; n++)
#pragma unroll
            for (int t = 0; t < 4; t++) acc[m][n][t] = 0.0f;

    // --- prefetch stage 0 into slot 0 ---
#pragma unroll
    for (int j = 0; j < 4; j++) {
        cp_async16(dA + j * 32 * ROW_B, Ag + (size_t)(j * 32) * D_INF);
        cp_async16(dB + j * 32 * ROW_B, Bg + (size_t)(j * 32) * D_INF);
    }
    CP_COMMIT();

    for (int i = 0; i < NIT; i++) {
        CP_WAIT(0);                // stage i resident (this thread); load(i+1)
                                   // not yet issued, so no overlap is lost.
        __syncthreads();           // resident block-wide; orders compute(i-1)
                                   // on the other slot before its refill.

        if (i + 1 < NIT) {
            const uint32_t so = (uint32_t)((i + 1) & 1) * STAGE_BYTES;
            const size_t k0 = (size_t)(i + 1) * BK;
#pragma unroll
            for (int j = 0; j < 4; j++) {
                cp_async16(dA + so + j * 32 * ROW_B, Ag + (size_t)(j * 32) * D_INF + k0);
                cp_async16(dB + so + j * 32 * ROW_B, Bg + (size_t)(j * 32) * D_INF + k0);
            }
            CP_COMMIT();
        }

        // compute stage i from slot i&1: 4 k-fragments of 16
        const uint32_t so = (uint32_t)(i & 1) * STAGE_BYTES;
        const uint32_t ab = sb + so + (uint32_t)(wm * 64) * ROW_B + aoff;
        const uint32_t bb = sb + so + A_BYTES + (uint32_t)(wn * 32) * ROW_B + boff;

#pragma unroll
        for (int kf = 0; kf < 4; kf++) {
            uint32_t af[4][4], bf[2][4];
#pragma unroll
            for (int mf = 0; mf < 4; mf++)
                LDSM_X4(af[mf], ab + (uint32_t)(mf * 16) * ROW_B + kf * 32);
#pragma unroll
            for (int nf2 = 0; nf2 < 2; nf2++)
                LDSM_X4(bf[nf2], bb + (uint32_t)(nf2 * 16) * ROW_B + kf * 32);
#pragma unroll
            for (int mf = 0; mf < 4; mf++)
#pragma unroll
                for (int nf = 0; nf < 4; nf++)
                    mma16816(acc[mf][nf], af[mf],
                             bf[nf >> 1][(nf & 1) * 2], bf[nf >> 1][(nf & 1) * 2 + 1]);
        }
    }

    // --- epilogue: c0,c1 -> (row, col); c2,c3 -> (row+8, col) ---
#pragma unroll
    for (int mf = 0; mf < 4; mf++) {
        const int row = bm * BM + wm * 64 + mf * 16 + (lane >> 2);
        float* r0 = C + (size_t)row * D_OUTF + bn * BN + wn * 32 + (lane & 3) * 2;
        float* r1 = r0 + (size_t)8 * D_OUTF;
#pragma unroll
        for (int nf = 0; nf < 4; nf++) {
            *(float2*)(r0 + nf * 8) = make_float2(acc[mf][nf][0], acc[mf][nf][1]);
            *(float2*)(r1 + nf * 8) = make_float2(acc[mf][nf][2], acc[mf][nf][3]);
        }
    }
}

// ---------------------------------------------------------------------------
// kernel_launch — graph-capturable, allocation-free.
// Inputs: x[f32], codes[i32], scales[f32], lora_A[f32], lora_B[f32]; out f32.
// ---------------------------------------------------------------------------
extern "C" void kernel_launch(void* const* d_in, const int* in_sizes, int n_in,
                              void* d_out, int out_size)
{
    const float* x      = (const float*)d_in[0];
    const int*   codes  = (const int*)  d_in[1];
    const float* scales = (const float*)d_in[2];
    const float* lora_A = (const float*)d_in[3];
    const float* lora_B = (const float*)d_in[4];
    float*       out    = (float*)d_out;

    const int M = in_sizes[0] / D_INF;   // 8192

    cudaFuncSetAttribute(hgemm_nt_kernel,
                         cudaFuncAttributeMaxDynamicSharedMemorySize, SMEM_TOTAL);

    const int xblk = (M * 1024) / 256;   // 8192
    build_inputs_kernel<<<WBLK + xblk, 256>>>(x, codes, scales, lora_A, lora_B);

    dim3 grid(D_OUTF / BN, M / BM);   // (32, 64)
    hgemm_nt_kernel<<<grid, 256, SMEM_TOTAL>>>(out);

    (void)n_in; (void)out_size;
}